// round 3
// baseline (speedup 1.0000x reference)
#include <cuda_runtime.h>
#include <math.h>

#define NSIG   (1 << 22)              // 4194304 = HOP * N_FRAMES
#define NFR    16384
#define NBIN   513
#define HOPSZ  256
#define OUTLEN ((NFR - 1) * HOPSZ)    // 4194048

// ------------------------- device scratch (static per rules) -------------------
__device__ float  g_f0[NFR];
__device__ float  g_f0up[NSIG];
__device__ float  g_lv[NSIG];                    // pair-sum levels 1..22 packed
__device__ float  g_saw[NSIG];
__device__ float  g_pulse[NSIG];
__device__ float  g_envTn[(size_t)NFR * NBIN];   // transposed log-envelopes [t][k]
__device__ float  g_envTp[(size_t)NFR * NBIN];
__device__ float  g_frames[(size_t)NFR * 1024];  // windowed synthesis frames
__device__ float2 g_tw[512];                     // exp(-2*pi*i*t/1024)
__device__ float  g_w[1024];                     // hann window

// ------------------------------- init tables -----------------------------------
__global__ void k_init() {
  int tid = threadIdx.x;                          // <<<1,1024>>>
  if (tid < 512) {
    double ang = -2.0 * 3.14159265358979323846 * (double)tid / 1024.0;
    g_tw[tid] = make_float2((float)cos(ang), (float)sin(ang));
  }
  g_w[tid] = 0.5f * (1.0f - cosf((float)tid * (6.28318530717958647692f / 1024.0f)));
}

// --------------------- impulse train (bit-replicates JAX) ----------------------
__global__ void k_exp(const float* __restrict__ log_f0) {
  int i = blockIdx.x * blockDim.x + threadIdx.x;
  if (i < NFR) g_f0[i] = expf(log_f0[i]);         // == libdevice __nv_expf (XLA:GPU)
}

__global__ void k_interp() {
  int i = blockIdx.x * blockDim.x + threadIdx.x;  // i < NSIG (exact grid)
  float fi  = (float)i;
  float pos = __fsub_rn(__fdiv_rn(__fadd_rn(fi, 0.5f), 256.0f), 0.5f);
  pos = fminf(fmaxf(pos, 0.0f), 16383.0f);
  float flo = floorf(pos);
  int lo = (int)flo;
  int hi = lo + 1; if (hi > 16383) hi = 16383;
  float frac = __fsub_rn(pos, flo);
  float a = __fmul_rn(g_f0[lo], __fsub_rn(1.0f, frac));
  float b = __fmul_rn(g_f0[hi], frac);
  g_f0up[i] = __fadd_rn(a, b);
}

// level l in 1..22: pairwise sums of level l-1 (level 0 = g_f0up)
__global__ void k_pairsum(int l) {
  int n = 1 << (22 - l);
  int i = blockIdx.x * blockDim.x + threadIdx.x;
  if (i >= n) return;
  const float* in = (l == 1) ? g_f0up : (g_lv + ((1 << 22) - (1 << (24 - l))));
  float* out = g_lv + ((1 << 22) - (1 << (23 - l)));
  out[i] = __fadd_rn(in[2 * i], in[2 * i + 1]);
}

// cumsum per jax associative_scan closed form: left-fold of dyadic blocks of [0..n]
__global__ void k_saw() {
  int n = blockIdx.x * blockDim.x + threadIdx.x;
  int m = n + 1;
  float acc = 0.0f;
  bool first = true;
  int start = 0;
  #pragma unroll
  for (int l = 22; l >= 0; --l) {
    if (m & (1 << l)) {
      float v = (l == 0) ? g_f0up[start]
                         : g_lv[((1 << 22) - (1 << (23 - l))) + (start >> l)];
      acc = first ? v : __fadd_rn(acc, v);
      first = false;
      start += (1 << l);
    }
  }
  float phase = __fdiv_rn(acc, 24000.0f);
  g_saw[n] = __fsub_rn(phase, floorf(phase));     // exact frac for phase >= 0
}

__global__ void k_imp() {
  int n = blockIdx.x * blockDim.x + threadIdx.x;
  float s0 = g_saw[n];
  float s1 = g_saw[(n + 1) & (NSIG - 1)];         // jnp.roll(saw, -1)
  float d  = __fdiv_rn(g_f0up[n], 24000.0f);
  g_pulse[n] = __fadd_rn(__fsub_rn(s0, s1), d);
}

// ------------------- envelope transpose [513][16384] -> [16384][513] ------------
__global__ void k_transpose(const float* __restrict__ in, int which) {
  __shared__ float tile[32][33];
  float* out = which ? g_envTp : g_envTn;
  int t0 = blockIdx.x * 32, k0 = blockIdx.y * 32;
  int x = t0 + threadIdx.x, y = k0 + threadIdx.y;
  if (y < NBIN) tile[threadIdx.y][threadIdx.x] = in[(size_t)y * NFR + x];
  __syncthreads();
  int tx = t0 + threadIdx.y, kx = k0 + threadIdx.x;
  if (kx < NBIN) out[(size_t)tx * NBIN + kx] = tile[threadIdx.x][threadIdx.y];
}

// --------------------- shared-memory Stockham radix-2 FFT, N=1024 ---------------
// 512 threads, input in a[] (caller synced), output in a[] (10 stages = even).
// Forward uses table twiddles exp(-i...); inverse conjugates (unscaled IDFT).
__device__ __forceinline__ void fft1024(float2* a, float2* b, const float2* tw,
                                        int tid, bool inverse) {
  float2* x = a;
  float2* y = b;
  int m = 1;
  #pragma unroll
  for (int s = 0; s < 10; s++) {
    int j = tid >> s;            // tid / m
    int k = tid & (m - 1);       // tid % m
    float2 c0 = x[tid];          // k + j*m
    float2 c1 = x[tid + 512];    // k + j*m + l*m  (l*m == 512)
    float2 w  = tw[j << s];      // exp(-2*pi*i*j/(2l)), index = j*(512/l)
    float wy  = inverse ? -w.y : w.y;
    float dx = c0.x - c1.x, dy = c0.y - c1.y;
    float2 sum = make_float2(c0.x + c1.x, c0.y + c1.y);
    float2 rot = make_float2(dx * w.x - dy * wy, dx * wy + dy * w.x);
    int o = k + 2 * j * m;
    y[o]     = sum;
    y[o + m] = rot;
    __syncthreads();
    float2* t2 = x; x = y; y = t2;
    m <<= 1;
  }
}

// ------------------------------ per-frame mega-kernel ---------------------------
// Frame t (block) = STFT frame t+1 of both signals, envelope filter, min-phase,
// combined synthesis iFFT, windowed frame store.
__global__ __launch_bounds__(512) void k_frames(const float* __restrict__ noise) {
  __shared__ float2 bufA[1024];
  __shared__ float2 bufB[1024];
  __shared__ float2 arrN[NBIN];
  __shared__ float2 arrP[NBIN];
  __shared__ float2 stw[512];

  int t   = blockIdx.x;
  int tid = threadIdx.x;

  stw[tid] = g_tw[tid];

  // load + window both signals, packed complex (noise + i*pulse)
  #pragma unroll
  for (int q = 0; q < 2; q++) {
    int n = tid + q * 512;
    int g = t * 256 - 256 + n;                 // reflect pad
    if (g < 0) g = -g;
    else if (g >= NSIG) g = 2 * NSIG - 2 - g;
    float w = g_w[n];
    bufA[n] = make_float2(noise[g] * w, g_pulse[g] * w);
  }
  __syncthreads();

  fft1024(bufA, bufB, stw, tid, false);        // Z in bufA

  // unpack two real FFTs; apply noise envelope immediately
  for (int k = tid; k <= 512; k += 512) {
    float2 z1 = bufA[k];
    float2 z2 = bufA[(1024 - k) & 1023];
    float en = expf(g_envTn[(size_t)t * NBIN + k]);
    arrN[k] = make_float2(0.5f * (z1.x + z2.x) * en, 0.5f * (z1.y - z2.y) * en);
    arrP[k] = make_float2(0.5f * (z1.y + z2.y),      0.5f * (z2.x - z1.x));
  }
  __syncthreads();

  // min-phase: symmetric real log-spectrum -> iFFT -> fold -> FFT -> exp
  #pragma unroll
  for (int q = 0; q < 2; q++) {
    int n = tid + q * 512;
    int k = (n <= 512) ? n : 1024 - n;
    bufA[n] = make_float2(g_envTp[(size_t)t * NBIN + k], 0.0f);
  }
  __syncthreads();

  fft1024(bufA, bufB, stw, tid, true);         // unscaled IDFT -> real cepstrum*1024

  #pragma unroll
  for (int q = 0; q < 2; q++) {
    int n = tid + q * 512;
    float c = bufA[n].x * (1.0f / 1024.0f);
    float f = (n == 0 || n == 512) ? 1.0f : (n < 512 ? 2.0f : 0.0f);
    bufA[n] = make_float2(c * f, 0.0f);
  }
  __syncthreads();

  fft1024(bufA, bufB, stw, tid, false);        // C = rfft(folded cep) in bufA

  // S[k] = Noi*En + Per*exp(C)
  for (int k = tid; k <= 512; k += 512) {
    float2 C = bufA[k];
    float mag = expf(C.x);
    float sn, cs;
    sincosf(C.y, &sn, &cs);
    float2 MP = make_float2(mag * cs, mag * sn);
    float2 P  = arrP[k];
    float2 PM = make_float2(P.x * MP.x - P.y * MP.y, P.x * MP.y + P.y * MP.x);
    arrN[k] = make_float2(arrN[k].x + PM.x, arrN[k].y + PM.y);
  }
  __syncthreads();

  // Hermitian extend -> synthesis iFFT -> window -> store frame
  #pragma unroll
  for (int q = 0; q < 2; q++) {
    int n = tid + q * 512;
    bufA[n] = (n <= 512) ? arrN[n]
                         : make_float2(arrN[1024 - n].x, -arrN[1024 - n].y);
  }
  __syncthreads();

  fft1024(bufA, bufB, stw, tid, true);

  #pragma unroll
  for (int q = 0; q < 2; q++) {
    int n = tid + q * 512;
    g_frames[(size_t)t * 1024 + n] = bufA[n].x * (1.0f / 1024.0f) * g_w[n];
  }
}

// ----------------------------- overlap-add + wsq -------------------------------
__global__ void k_ola(float* __restrict__ out) {
  int i = blockIdx.x * blockDim.x + threadIdx.x;
  if (i >= OUTLEN) return;
  int p = i + 512;                 // position in padded iSTFT output
  int jhi = p >> 8;
  int jlo = jhi - 3;
  if (jlo < 0) jlo = 0;
  if (jhi > NFR - 1) jhi = NFR - 1;
  float acc = 0.0f, ws = 0.0f;
  #pragma unroll 4
  for (int j = jlo; j <= jhi; j++) {
    int n = p - (j << 8);
    acc += g_frames[(size_t)j * 1024 + n];
    float w = g_w[n];
    ws += w * w;
  }
  out[i] = acc / fmaxf(ws, 1e-11f);
}

// --------------------------------- launcher ------------------------------------
extern "C" void kernel_launch(void* const* d_in, const int* in_sizes, int n_in,
                              void* d_out, int out_size) {
  const float* log_f0  = (const float*)d_in[0];
  const float* env_noi = (const float*)d_in[1];
  const float* env_per = (const float*)d_in[2];
  const float* noise   = (const float*)d_in[3];
  float* out = (float*)d_out;

  k_init<<<1, 1024>>>();
  k_exp<<<NFR / 256, 256>>>(log_f0);
  k_interp<<<NSIG / 256, 256>>>();
  for (int l = 1; l <= 22; l++) {
    int n = 1 << (22 - l);
    int grid = (n + 255) / 256;
    k_pairsum<<<grid, 256>>>(l);
  }
  k_saw<<<NSIG / 256, 256>>>();
  k_imp<<<NSIG / 256, 256>>>();
  dim3 tb(32, 32);
  dim3 tg(NFR / 32, (NBIN + 31) / 32);
  k_transpose<<<tg, tb>>>(env_noi, 0);
  k_transpose<<<tg, tb>>>(env_per, 1);
  k_frames<<<NFR, 512>>>(noise);
  k_ola<<<(OUTLEN + 255) / 256, 256>>>(out);
}

// round 4
// speedup vs baseline: 1.3067x; 1.3067x over previous
#include <cuda_runtime.h>
#include <math.h>

#define NSIG   (1 << 22)              // 4194304 = HOP * N_FRAMES
#define NFR    16384
#define NBIN   513
#define HOPSZ  256
#define OUTLEN ((NFR - 1) * HOPSZ)    // 4194048
#define LVOFF(l) ((1 << 22) - (1 << (23 - (l))))

// ------------------------- device scratch (static per rules) -------------------
__device__ float  g_f0[NFR];
__device__ float  g_f0up[NSIG];
__device__ float  g_lv[NSIG];                    // pair-sum levels 1..22 packed
__device__ float  g_saw[NSIG];
__device__ float  g_pulse[NSIG];
__device__ float  g_envTn[(size_t)NFR * NBIN];   // transposed log-envelopes [t][k]
__device__ float  g_envTp[(size_t)NFR * NBIN];
__device__ float  g_frames[(size_t)NFR * 1024];  // windowed synthesis frames
__device__ float2 g_tw[768];                     // exp(-2*pi*i*t/1024), t<768
__device__ float  g_w[1024];                     // hann window

// ------------------------------- init tables -----------------------------------
__global__ void k_init() {
  int tid = threadIdx.x;                          // <<<1,1024>>>
  if (tid < 768) {
    double ang = -2.0 * 3.14159265358979323846 * (double)tid / 1024.0;
    g_tw[tid] = make_float2((float)cos(ang), (float)sin(ang));
  }
  g_w[tid] = 0.5f * (1.0f - cosf((float)tid * (6.28318530717958647692f / 1024.0f)));
}

// --------------------- impulse train (bit-replicates JAX) ----------------------
__global__ void k_exp(const float* __restrict__ log_f0) {
  int i = blockIdx.x * blockDim.x + threadIdx.x;
  if (i < NFR) g_f0[i] = expf(log_f0[i]);         // == libdevice __nv_expf (XLA:GPU)
}

__global__ void k_interp() {
  int i = blockIdx.x * blockDim.x + threadIdx.x;  // i < NSIG (exact grid)
  float fi  = (float)i;
  float pos = __fsub_rn(__fdiv_rn(__fadd_rn(fi, 0.5f), 256.0f), 0.5f);
  pos = fminf(fmaxf(pos, 0.0f), 16383.0f);
  float flo = floorf(pos);
  int lo = (int)flo;
  int hi = lo + 1; if (hi > 16383) hi = 16383;
  float frac = __fsub_rn(pos, flo);
  float a = __fmul_rn(g_f0[lo], __fsub_rn(1.0f, frac));
  float b = __fmul_rn(g_f0[hi], frac);
  g_f0up[i] = __fadd_rn(a, b);
}

// pair-sum levels 1..10, block-local (identical __fadd_rn tree as level-by-level)
__global__ __launch_bounds__(512) void k_scan_lo() {
  __shared__ float s[1024];
  int b = blockIdx.x, t = threadIdx.x;
  s[t]       = g_f0up[b * 1024 + t];
  s[t + 512] = g_f0up[b * 1024 + t + 512];
  __syncthreads();
  int n = 512;
  #pragma unroll
  for (int l = 1; l <= 10; l++) {
    float v = 0.0f;
    if (t < n) v = __fadd_rn(s[2 * t], s[2 * t + 1]);
    __syncthreads();
    if (t < n) {
      s[t] = v;
      g_lv[LVOFF(l) + b * n + t] = v;
    }
    __syncthreads();
    n >>= 1;
  }
}

// pair-sum levels 11..22, single block (level 10 has 4096 entries)
__global__ __launch_bounds__(1024) void k_scan_hi() {
  __shared__ float s[4096];
  int t = threadIdx.x;
  #pragma unroll
  for (int q = 0; q < 4; q++) s[t + q * 1024] = g_lv[LVOFF(10) + t + q * 1024];
  __syncthreads();
  int n = 2048;
  for (int l = 11; l <= 22; l++) {
    float v0 = 0.0f, v1 = 0.0f;
    if (t < n)        v0 = __fadd_rn(s[2 * t], s[2 * t + 1]);
    if (t + 1024 < n) v1 = __fadd_rn(s[2 * (t + 1024)], s[2 * (t + 1024) + 1]);
    __syncthreads();
    if (t < n)        { s[t] = v0;        g_lv[LVOFF(l) + t] = v0; }
    if (t + 1024 < n) { s[t + 1024] = v1; g_lv[LVOFF(l) + t + 1024] = v1; }
    __syncthreads();
    n >>= 1;
  }
}

// cumsum per jax associative_scan closed form: left-fold of dyadic blocks of [0..n]
__global__ void k_saw() {
  int n = blockIdx.x * blockDim.x + threadIdx.x;
  int m = n + 1;
  float acc = 0.0f;
  bool first = true;
  int start = 0;
  #pragma unroll
  for (int l = 22; l >= 0; --l) {
    if (m & (1 << l)) {
      float v = (l == 0) ? g_f0up[start]
                         : g_lv[LVOFF(l) + (start >> l)];
      acc = first ? v : __fadd_rn(acc, v);
      first = false;
      start += (1 << l);
    }
  }
  float phase = __fdiv_rn(acc, 24000.0f);
  g_saw[n] = __fsub_rn(phase, floorf(phase));     // exact frac for phase >= 0
}

__global__ void k_imp() {
  int n = blockIdx.x * blockDim.x + threadIdx.x;
  float s0 = g_saw[n];
  float s1 = g_saw[(n + 1) & (NSIG - 1)];         // jnp.roll(saw, -1)
  float d  = __fdiv_rn(g_f0up[n], 24000.0f);
  g_pulse[n] = __fadd_rn(__fsub_rn(s0, s1), d);
}

// ------------------- envelope transpose [513][16384] -> [16384][513] ------------
__global__ void k_transpose(const float* __restrict__ in, int which) {
  __shared__ float tile[32][33];
  float* out = which ? g_envTp : g_envTn;
  int t0 = blockIdx.x * 32, k0 = blockIdx.y * 32;
  int x = t0 + threadIdx.x, y = k0 + threadIdx.y;
  if (y < NBIN) tile[threadIdx.y][threadIdx.x] = in[(size_t)y * NFR + x];
  __syncthreads();
  int tx = t0 + threadIdx.y, kx = k0 + threadIdx.x;
  if (kx < NBIN) out[(size_t)tx * NBIN + kx] = tile[threadIdx.x][threadIdx.y];
}

// --------------------- shared-memory Stockham radix-4 FFT, N=1024 ---------------
// DIF Stockham: b = 4-pt DFT of strided inputs, twiddle applied after butterfly.
// 256 threads. Input in A (caller synced). 5 stages -> result lands in B.
__device__ __forceinline__ float2 cmul_s(float2 b, float2 w, float sgn) {
  float wy = sgn * w.y;
  return make_float2(b.x * w.x - b.y * wy, b.x * wy + b.y * w.x);
}

__device__ __forceinline__ void fft1024_r4(float2* A, float2* B, const float2* tw,
                                           int t, bool inv) {
  float2* x = A;
  float2* y = B;
  const float sgn = inv ? -1.0f : 1.0f;
  int m = 1;
  #pragma unroll
  for (int s = 0; s < 5; s++) {
    int j = t >> (2 * s);
    int k = t & (m - 1);
    float2 c0 = x[t];
    float2 c1 = x[t + 256];
    float2 c2 = x[t + 512];
    float2 c3 = x[t + 768];
    float ax = c0.x + c2.x, ay = c0.y + c2.y;
    float bx = c1.x + c3.x, by = c1.y + c3.y;
    float dx = c0.x - c2.x, dy = c0.y - c2.y;
    float ex = c1.x - c3.x, ey = c1.y - c3.y;
    float2 b0 = make_float2(ax + bx, ay + by);
    float2 b2 = make_float2(ax - bx, ay - by);
    float2 b1, b3;
    if (!inv) {                       // b1 = d - i*e, b3 = d + i*e
      b1 = make_float2(dx + ey, dy - ex);
      b3 = make_float2(dx - ey, dy + ex);
    } else {                          // conjugated kernel
      b1 = make_float2(dx - ey, dy + ex);
      b3 = make_float2(dx + ey, dy - ex);
    }
    int jm = j * m;                   // jm <= 256 - m  ->  3*jm < 768
    float2 w1 = tw[jm];
    float2 w2 = tw[2 * jm];
    float2 w3 = tw[3 * jm];
    int o = k + 4 * jm;
    y[o]         = b0;
    y[o + m]     = cmul_s(b1, w1, sgn);
    y[o + 2 * m] = cmul_s(b2, w2, sgn);
    y[o + 3 * m] = cmul_s(b3, w3, sgn);
    __syncthreads();
    float2* tp = x; x = y; y = tp;
    m <<= 2;
  }
}

// ------------------------------ per-frame mega-kernel ---------------------------
// Block t = STFT frame t+1 of both signals, envelope filter, min-phase,
// combined synthesis iFFT, windowed frame store.  256 threads.
__global__ __launch_bounds__(256) void k_frames(const float* __restrict__ noise) {
  __shared__ float2 bufA[1024];
  __shared__ float2 bufB[1024];
  __shared__ float2 arrN[NBIN];
  __shared__ float2 arrP[NBIN];
  __shared__ float2 stw[768];

  int t   = blockIdx.x;
  int tid = threadIdx.x;

  #pragma unroll
  for (int i = tid; i < 768; i += 256) stw[i] = g_tw[i];

  // load + window both signals, packed complex (noise + i*pulse)
  #pragma unroll
  for (int q = 0; q < 4; q++) {
    int n = tid + q * 256;
    int g = t * 256 - 256 + n;                 // reflect pad
    if (g < 0) g = -g;
    else if (g >= NSIG) g = 2 * NSIG - 2 - g;
    float w = g_w[n];
    bufA[n] = make_float2(noise[g] * w, g_pulse[g] * w);
  }
  __syncthreads();

  fft1024_r4(bufA, bufB, stw, tid, false);     // Z in bufB

  // unpack two real FFTs; apply noise envelope immediately
  #pragma unroll
  for (int k = tid; k <= 512; k += 256) {
    float2 z1 = bufB[k];
    float2 z2 = bufB[(1024 - k) & 1023];
    float en = expf(g_envTn[(size_t)t * NBIN + k]);
    arrN[k] = make_float2(0.5f * (z1.x + z2.x) * en, 0.5f * (z1.y - z2.y) * en);
    arrP[k] = make_float2(0.5f * (z1.y + z2.y),      0.5f * (z2.x - z1.x));
  }

  // min-phase input: symmetric real log-spectrum
  #pragma unroll
  for (int q = 0; q < 4; q++) {
    int n = tid + q * 256;
    int k = (n <= 512) ? n : 1024 - n;
    bufA[n] = make_float2(g_envTp[(size_t)t * NBIN + k], 0.0f);
  }
  __syncthreads();

  fft1024_r4(bufA, bufB, stw, tid, true);      // unscaled IDFT -> cepstrum*1024 in bufB

  // fold
  #pragma unroll
  for (int q = 0; q < 4; q++) {
    int n = tid + q * 256;
    float c = bufB[n].x * (1.0f / 1024.0f);
    float f = (n == 0 || n == 512) ? 1.0f : (n < 512 ? 2.0f : 0.0f);
    bufA[n] = make_float2(c * f, 0.0f);
  }
  __syncthreads();

  fft1024_r4(bufA, bufB, stw, tid, false);     // C = rfft(folded cep) in bufB

  // S[k] = Noi*En + Per*exp(C)
  #pragma unroll
  for (int k = tid; k <= 512; k += 256) {
    float2 C = bufB[k];
    float mag = expf(C.x);
    float sn, cs;
    sincosf(C.y, &sn, &cs);
    float2 MP = make_float2(mag * cs, mag * sn);
    float2 P  = arrP[k];
    float2 PM = make_float2(P.x * MP.x - P.y * MP.y, P.x * MP.y + P.y * MP.x);
    arrN[k] = make_float2(arrN[k].x + PM.x, arrN[k].y + PM.y);
  }
  __syncthreads();

  // Hermitian extend -> synthesis iFFT -> window -> store frame
  #pragma unroll
  for (int q = 0; q < 4; q++) {
    int n = tid + q * 256;
    bufA[n] = (n <= 512) ? arrN[n]
                         : make_float2(arrN[1024 - n].x, -arrN[1024 - n].y);
  }
  __syncthreads();

  fft1024_r4(bufA, bufB, stw, tid, true);      // real frame in bufB (x1024)

  #pragma unroll
  for (int q = 0; q < 4; q++) {
    int n = tid + q * 256;
    g_frames[(size_t)t * 1024 + n] = bufB[n].x * (1.0f / 1024.0f) * g_w[n];
  }
}

// ----------------------------- overlap-add + wsq -------------------------------
__global__ void k_ola(float* __restrict__ out) {
  int i = blockIdx.x * blockDim.x + threadIdx.x;
  if (i >= OUTLEN) return;
  int p = i + 512;                 // position in padded iSTFT output
  int jhi = p >> 8;
  int jlo = jhi - 3;
  if (jlo < 0) jlo = 0;
  if (jhi > NFR - 1) jhi = NFR - 1;
  float acc = 0.0f, ws = 0.0f;
  #pragma unroll 4
  for (int j = jlo; j <= jhi; j++) {
    int n = p - (j << 8);
    acc += g_frames[(size_t)j * 1024 + n];
    float w = g_w[n];
    ws += w * w;
  }
  out[i] = acc / fmaxf(ws, 1e-11f);
}

// --------------------------------- launcher ------------------------------------
extern "C" void kernel_launch(void* const* d_in, const int* in_sizes, int n_in,
                              void* d_out, int out_size) {
  const float* log_f0  = (const float*)d_in[0];
  const float* env_noi = (const float*)d_in[1];
  const float* env_per = (const float*)d_in[2];
  const float* noise   = (const float*)d_in[3];
  float* out = (float*)d_out;

  k_init<<<1, 1024>>>();
  k_exp<<<NFR / 256, 256>>>(log_f0);
  k_interp<<<NSIG / 256, 256>>>();
  k_scan_lo<<<NSIG / 1024, 512>>>();
  k_scan_hi<<<1, 1024>>>();
  k_saw<<<NSIG / 256, 256>>>();
  k_imp<<<NSIG / 256, 256>>>();
  dim3 tb(32, 32);
  dim3 tg(NFR / 32, (NBIN + 31) / 32);
  k_transpose<<<tg, tb>>>(env_noi, 0);
  k_transpose<<<tg, tb>>>(env_per, 1);
  k_frames<<<NFR, 256>>>(noise);
  k_ola<<<(OUTLEN + 255) / 256, 256>>>(out);
}

// round 5
// speedup vs baseline: 1.6974x; 1.2990x over previous
#include <cuda_runtime.h>
#include <math.h>

#define NSIG   (1 << 22)              // 4194304 = HOP * N_FRAMES
#define NFR    16384
#define NBIN   513
#define HOPSZ  256
#define OUTLEN ((NFR - 1) * HOPSZ)    // 4194048
#define LVOFF(l) ((1 << 22) - (1 << (23 - (l))))

// ------------------------- device scratch (static per rules) -------------------
__device__ float  g_f0[NFR];
__device__ float  g_f0up[NSIG];
__device__ float  g_lv[NSIG];                    // pair-sum levels 1..22 packed
__device__ float  g_saw[NSIG];
__device__ float  g_pulse[NSIG];
__device__ float  g_envTn[(size_t)NFR * NBIN];   // transposed log-envelopes [t][k]
__device__ float  g_envTp[(size_t)NFR * NBIN];
__device__ float  g_frames[(size_t)NFR * 1024];  // windowed synthesis frames
__device__ float2 g_tw[768];                     // exp(-2*pi*i*t/1024), t<768
__device__ float  g_w[1024];                     // hann window

// ------------------------------- init tables -----------------------------------
__global__ void k_init() {
  int tid = threadIdx.x;                          // <<<1,1024>>>
  if (tid < 768) {
    double ang = -2.0 * 3.14159265358979323846 * (double)tid / 1024.0;
    g_tw[tid] = make_float2((float)cos(ang), (float)sin(ang));
  }
  g_w[tid] = 0.5f * (1.0f - cosf((float)tid * (6.28318530717958647692f / 1024.0f)));
}

// --------------------- impulse train (bit-replicates JAX) ----------------------
__global__ void k_exp(const float* __restrict__ log_f0) {
  int i = blockIdx.x * blockDim.x + threadIdx.x;
  if (i < NFR) g_f0[i] = expf(log_f0[i]);         // == libdevice __nv_expf (XLA:GPU)
}

__global__ void k_interp() {
  int i = blockIdx.x * blockDim.x + threadIdx.x;  // i < NSIG (exact grid)
  float fi  = (float)i;
  float pos = __fsub_rn(__fdiv_rn(__fadd_rn(fi, 0.5f), 256.0f), 0.5f);
  pos = fminf(fmaxf(pos, 0.0f), 16383.0f);
  float flo = floorf(pos);
  int lo = (int)flo;
  int hi = lo + 1; if (hi > 16383) hi = 16383;
  float frac = __fsub_rn(pos, flo);
  float a = __fmul_rn(g_f0[lo], __fsub_rn(1.0f, frac));
  float b = __fmul_rn(g_f0[hi], frac);
  g_f0up[i] = __fadd_rn(a, b);
}

// pair-sum levels 1..10 (levels 1-2 in registers; identical __fadd_rn tree)
__global__ __launch_bounds__(256) void k_scan_lo() {
  __shared__ float s[256];
  int b = blockIdx.x, t = threadIdx.x;
  float4 x = ((const float4*)g_f0up)[b * 256 + t];
  float a0 = __fadd_rn(x.x, x.y);
  float a1 = __fadd_rn(x.z, x.w);
  float c  = __fadd_rn(a0, a1);
  ((float2*)(g_lv + LVOFF(1)))[b * 256 + t] = make_float2(a0, a1);
  g_lv[LVOFF(2) + b * 256 + t] = c;
  s[t] = c;
  __syncthreads();
  int n = 128;
  #pragma unroll
  for (int l = 3; l <= 10; l++) {
    float v = 0.0f;
    if (t < n) v = __fadd_rn(s[2 * t], s[2 * t + 1]);
    __syncthreads();
    if (t < n) { s[t] = v; g_lv[LVOFF(l) + b * n + t] = v; }
    __syncthreads();
    n >>= 1;
  }
}

// pair-sum levels 11..22, single block (level 10 has 4096 entries)
__global__ __launch_bounds__(1024) void k_scan_hi() {
  __shared__ float s[4096];
  int t = threadIdx.x;
  #pragma unroll
  for (int q = 0; q < 4; q++) s[t + q * 1024] = g_lv[LVOFF(10) + t + q * 1024];
  __syncthreads();
  int n = 2048;
  for (int l = 11; l <= 22; l++) {
    float v0 = 0.0f, v1 = 0.0f;
    if (t < n)        v0 = __fadd_rn(s[2 * t], s[2 * t + 1]);
    if (t + 1024 < n) v1 = __fadd_rn(s[2 * (t + 1024)], s[2 * (t + 1024) + 1]);
    __syncthreads();
    if (t < n)        { s[t] = v0;        g_lv[LVOFF(l) + t] = v0; }
    if (t + 1024 < n) { s[t + 1024] = v1; g_lv[LVOFF(l) + t + 1024] = v1; }
    __syncthreads();
    n >>= 1;
  }
}

// cumsum per jax associative_scan closed form: left-fold of dyadic blocks of [0..n]
__global__ void k_saw() {
  int n = blockIdx.x * blockDim.x + threadIdx.x;
  int m = n + 1;
  float acc = 0.0f;
  bool first = true;
  int start = 0;
  #pragma unroll
  for (int l = 22; l >= 0; --l) {
    if (m & (1 << l)) {
      float v = (l == 0) ? g_f0up[start]
                         : g_lv[LVOFF(l) + (start >> l)];
      acc = first ? v : __fadd_rn(acc, v);
      first = false;
      start += (1 << l);
    }
  }
  float phase = __fdiv_rn(acc, 24000.0f);
  g_saw[n] = __fsub_rn(phase, floorf(phase));     // exact frac for phase >= 0
}

__global__ void k_imp() {
  int n = blockIdx.x * blockDim.x + threadIdx.x;
  float s0 = g_saw[n];
  float s1 = g_saw[(n + 1) & (NSIG - 1)];         // jnp.roll(saw, -1)
  float d  = __fdiv_rn(g_f0up[n], 24000.0f);
  g_pulse[n] = __fadd_rn(__fsub_rn(s0, s1), d);
}

// ------------------- envelope transpose [513][16384] -> [16384][513] ------------
__global__ void k_transpose(const float* __restrict__ in, int which) {
  __shared__ float tile[32][33];
  float* out = which ? g_envTp : g_envTn;
  int t0 = blockIdx.x * 32, k0 = blockIdx.y * 32;
  int x = t0 + threadIdx.x, y = k0 + threadIdx.y;
  if (y < NBIN) tile[threadIdx.y][threadIdx.x] = in[(size_t)y * NFR + x];
  __syncthreads();
  int tx = t0 + threadIdx.y, kx = k0 + threadIdx.x;
  if (kx < NBIN) out[(size_t)tx * NBIN + kx] = tile[threadIdx.x][threadIdx.y];
}

// --------------------- shared-memory Stockham radix-4 FFT, N=1024 ---------------
// 256 threads. Input in A (caller synced). 5 stages -> result lands in B.
__device__ __forceinline__ float2 cmul_s(float2 b, float2 w, float sgn) {
  float wy = sgn * w.y;
  return make_float2(b.x * w.x - b.y * wy, b.x * wy + b.y * w.x);
}

__device__ __forceinline__ void fft1024_r4(float2* A, float2* B, const float2* tw,
                                           int t, bool inv) {
  float2* x = A;
  float2* y = B;
  const float sgn = inv ? -1.0f : 1.0f;
  int m = 1;
  #pragma unroll
  for (int s = 0; s < 5; s++) {
    int j = t >> (2 * s);
    int k = t & (m - 1);
    float2 c0 = x[t];
    float2 c1 = x[t + 256];
    float2 c2 = x[t + 512];
    float2 c3 = x[t + 768];
    float ax = c0.x + c2.x, ay = c0.y + c2.y;
    float bx = c1.x + c3.x, by = c1.y + c3.y;
    float dx = c0.x - c2.x, dy = c0.y - c2.y;
    float ex = c1.x - c3.x, ey = c1.y - c3.y;
    float2 b0 = make_float2(ax + bx, ay + by);
    float2 b2 = make_float2(ax - bx, ay - by);
    float2 b1, b3;
    if (!inv) {
      b1 = make_float2(dx + ey, dy - ex);
      b3 = make_float2(dx - ey, dy + ex);
    } else {
      b1 = make_float2(dx - ey, dy + ex);
      b3 = make_float2(dx + ey, dy - ex);
    }
    int jm = j * m;
    float2 w1 = tw[jm];
    float2 w2 = tw[2 * jm];
    float2 w3 = tw[3 * jm];
    int o = k + 4 * jm;
    y[o]         = b0;
    y[o + m]     = cmul_s(b1, w1, sgn);
    y[o + 2 * m] = cmul_s(b2, w2, sgn);
    y[o + 3 * m] = cmul_s(b3, w3, sgn);
    __syncthreads();
    float2* tp = x; x = y; y = tp;
    m <<= 2;
  }
}

// ------------------------------ per-frame-pair mega-kernel ----------------------
// Block b handles frames t0=2b, t1=2b+1. 5 complex FFTs per 2 frames:
//   2x analysis (noise+i*pulse per frame), 1x packed min-phase iDFT (real even x2),
//   1x packed folded-cepstrum FFT (real x2), 1x packed synthesis iFFT (herm x2).
__global__ __launch_bounds__(256) void k_frames(const float* __restrict__ noise) {
  __shared__ float2 bufA[1024];
  __shared__ float2 bufB[1024];
  __shared__ float2 arrN0[NBIN], arrP0[NBIN];
  __shared__ float2 arrN1[NBIN], arrP1[NBIN];
  __shared__ float2 stw[768];

  int b   = blockIdx.x;
  int t0  = 2 * b, t1 = 2 * b + 1;
  int tid = threadIdx.x;

  #pragma unroll
  for (int i = tid; i < 768; i += 256) stw[i] = g_tw[i];

  // ---- analysis FFT, frame t0 (noise + i*pulse) ----
  #pragma unroll
  for (int q = 0; q < 4; q++) {
    int n = tid + q * 256;
    int g = t0 * 256 - 256 + n;                // reflect pad
    if (g < 0) g = -g;
    else if (g >= NSIG) g = 2 * NSIG - 2 - g;
    float w = g_w[n];
    bufA[n] = make_float2(noise[g] * w, g_pulse[g] * w);
  }
  __syncthreads();
  fft1024_r4(bufA, bufB, stw, tid, false);

  // unpack t0 (+ noise envelope), and load frame t1 into bufA
  #pragma unroll
  for (int k = tid; k <= 512; k += 256) {
    float2 z1 = bufB[k];
    float2 z2 = bufB[(1024 - k) & 1023];
    float en = __expf(g_envTn[(size_t)t0 * NBIN + k]);
    arrN0[k] = make_float2(0.5f * (z1.x + z2.x) * en, 0.5f * (z1.y - z2.y) * en);
    arrP0[k] = make_float2(0.5f * (z1.y + z2.y),      0.5f * (z2.x - z1.x));
  }
  #pragma unroll
  for (int q = 0; q < 4; q++) {
    int n = tid + q * 256;
    int g = t1 * 256 - 256 + n;
    if (g < 0) g = -g;
    else if (g >= NSIG) g = 2 * NSIG - 2 - g;
    float w = g_w[n];
    bufA[n] = make_float2(noise[g] * w, g_pulse[g] * w);
  }
  __syncthreads();

  // ---- analysis FFT, frame t1 ----
  fft1024_r4(bufA, bufB, stw, tid, false);

  #pragma unroll
  for (int k = tid; k <= 512; k += 256) {
    float2 z1 = bufB[k];
    float2 z2 = bufB[(1024 - k) & 1023];
    float en = __expf(g_envTn[(size_t)t1 * NBIN + k]);
    arrN1[k] = make_float2(0.5f * (z1.x + z2.x) * en, 0.5f * (z1.y - z2.y) * en);
    arrP1[k] = make_float2(0.5f * (z1.y + z2.y),      0.5f * (z2.x - z1.x));
  }
  // packed min-phase input: v_t0 + i*v_t1 (both real even)
  #pragma unroll
  for (int q = 0; q < 4; q++) {
    int n = tid + q * 256;
    int k = (n <= 512) ? n : 1024 - n;
    bufA[n] = make_float2(g_envTp[(size_t)t0 * NBIN + k],
                          g_envTp[(size_t)t1 * NBIN + k]);
  }
  __syncthreads();

  // ---- packed min-phase iDFT: Re = 1024*cep_t0, Im = 1024*cep_t1 ----
  fft1024_r4(bufA, bufB, stw, tid, true);

  // fold both cepstra
  #pragma unroll
  for (int q = 0; q < 4; q++) {
    int n = tid + q * 256;
    float f = (n == 0 || n == 512) ? 1.0f : (n < 512 ? 2.0f : 0.0f);
    float sc = f * (1.0f / 1024.0f);
    bufA[n] = make_float2(bufB[n].x * sc, bufB[n].y * sc);
  }
  __syncthreads();

  // ---- packed forward FFT of folded cepstra ----
  fft1024_r4(bufA, bufB, stw, tid, false);

  // Hermitian unpack -> C0,C1; min-phase exp; combine; build packed synth spectrum
  #pragma unroll
  for (int k = tid; k <= 512; k += 256) {
    float2 z  = bufB[k];
    float2 zm = bufB[(1024 - k) & 1023];
    float2 C0 = make_float2(0.5f * (z.x + zm.x),  0.5f * (z.y - zm.y));
    float2 C1 = make_float2(0.5f * (z.y + zm.y), -0.5f * (z.x - zm.x));
    float sn, cs;
    float m0 = __expf(C0.x);
    __sincosf(C0.y, &sn, &cs);
    float2 MP0 = make_float2(m0 * cs, m0 * sn);
    float m1 = __expf(C1.x);
    __sincosf(C1.y, &sn, &cs);
    float2 MP1 = make_float2(m1 * cs, m1 * sn);

    float2 P0 = arrP0[k], P1 = arrP1[k];
    float2 S0 = make_float2(arrN0[k].x + P0.x * MP0.x - P0.y * MP0.y,
                            arrN0[k].y + P0.x * MP0.y + P0.y * MP0.x);
    float2 S1 = make_float2(arrN1[k].x + P1.x * MP1.x - P1.y * MP1.y,
                            arrN1[k].y + P1.x * MP1.y + P1.y * MP1.x);
    if (k == 0 || k == 512) { S0.y = 0.0f; S1.y = 0.0f; }  // irfft drops these

    // z[k] = S0full + i*S1full
    bufA[k] = make_float2(S0.x - S1.y, S0.y + S1.x);
    if (k > 0 && k < 512)
      bufA[1024 - k] = make_float2(S0.x + S1.y, S1.x - S0.y);
  }
  __syncthreads();

  // ---- packed synthesis iFFT: Re = 1024*frame_t0, Im = 1024*frame_t1 ----
  fft1024_r4(bufA, bufB, stw, tid, true);

  #pragma unroll
  for (int q = 0; q < 4; q++) {
    int n = tid + q * 256;
    float ws = (1.0f / 1024.0f) * g_w[n];
    float2 v = bufB[n];
    g_frames[(size_t)t0 * 1024 + n] = v.x * ws;
    g_frames[(size_t)t1 * 1024 + n] = v.y * ws;
  }
}

// ----------------------------- overlap-add + wsq -------------------------------
__global__ void k_ola(float* __restrict__ out) {
  int i = blockIdx.x * blockDim.x + threadIdx.x;
  if (i >= OUTLEN) return;
  int p = i + 512;                 // position in padded iSTFT output
  int jhi = p >> 8;
  int jlo = jhi - 3;
  if (jlo < 0) jlo = 0;
  if (jhi > NFR - 1) jhi = NFR - 1;
  float acc = 0.0f, ws = 0.0f;
  #pragma unroll 4
  for (int j = jlo; j <= jhi; j++) {
    int n = p - (j << 8);
    acc += g_frames[(size_t)j * 1024 + n];
    float w = g_w[n];
    ws += w * w;
  }
  out[i] = acc / fmaxf(ws, 1e-11f);
}

// --------------------------------- launcher ------------------------------------
extern "C" void kernel_launch(void* const* d_in, const int* in_sizes, int n_in,
                              void* d_out, int out_size) {
  const float* log_f0  = (const float*)d_in[0];
  const float* env_noi = (const float*)d_in[1];
  const float* env_per = (const float*)d_in[2];
  const float* noise   = (const float*)d_in[3];
  float* out = (float*)d_out;

  k_init<<<1, 1024>>>();
  k_exp<<<NFR / 256, 256>>>(log_f0);
  k_interp<<<NSIG / 256, 256>>>();
  k_scan_lo<<<NSIG / 1024, 256>>>();
  k_scan_hi<<<1, 1024>>>();
  k_saw<<<NSIG / 256, 256>>>();
  k_imp<<<NSIG / 256, 256>>>();
  dim3 tb(32, 32);
  dim3 tg(NFR / 32, (NBIN + 31) / 32);
  k_transpose<<<tg, tb>>>(env_noi, 0);
  k_transpose<<<tg, tb>>>(env_per, 1);
  k_frames<<<NFR / 2, 256>>>(noise);
  k_ola<<<(OUTLEN + 255) / 256, 256>>>(out);
}

// round 6
// speedup vs baseline: 1.8700x; 1.1017x over previous
#include <cuda_runtime.h>
#include <math.h>

#define NSIG   (1 << 22)              // 4194304 = HOP * N_FRAMES
#define NFR    16384
#define NBIN   513
#define HOPSZ  256
#define OUTLEN ((NFR - 1) * HOPSZ)    // 4194048
#define LVOFF(l) ((1 << 22) - (1 << (23 - (l))))

// ------------------------- device scratch (static per rules) -------------------
__device__ float  g_f0[NFR];
__device__ float  g_f0up[NSIG];
__device__ float  g_lv[NSIG];                    // pair-sum levels 1..22 packed
__device__ float  g_pulse[NSIG];
__device__ float  g_envTn[(size_t)NFR * NBIN];   // transposed log-envelopes [t][k]
__device__ float  g_envTp[(size_t)NFR * NBIN];
__device__ float  g_frames[(size_t)NFR * 1024];  // windowed synthesis frames
__device__ float2 g_tw[256];                     // exp(-2*pi*i*t/1024), t<256
__device__ float  g_w[1024];                     // hann window

// ------------------------------- init tables -----------------------------------
__global__ void k_init() {
  int tid = threadIdx.x;                          // <<<1,1024>>>
  if (tid < 256) {
    double ang = -2.0 * 3.14159265358979323846 * (double)tid / 1024.0;
    g_tw[tid] = make_float2((float)cos(ang), (float)sin(ang));
  }
  g_w[tid] = 0.5f * (1.0f - cosf((float)tid * (6.28318530717958647692f / 1024.0f)));
}

// --------------------- impulse train (bit-replicates JAX) ----------------------
__global__ void k_exp(const float* __restrict__ log_f0) {
  int i = blockIdx.x * blockDim.x + threadIdx.x;
  if (i < NFR) g_f0[i] = expf(log_f0[i]);         // == libdevice __nv_expf (XLA:GPU)
}

__global__ void k_interp() {
  int i = blockIdx.x * blockDim.x + threadIdx.x;  // i < NSIG (exact grid)
  float fi  = (float)i;
  float pos = __fsub_rn(__fdiv_rn(__fadd_rn(fi, 0.5f), 256.0f), 0.5f);
  pos = fminf(fmaxf(pos, 0.0f), 16383.0f);
  float flo = floorf(pos);
  int lo = (int)flo;
  int hi = lo + 1; if (hi > 16383) hi = 16383;
  float frac = __fsub_rn(pos, flo);
  float a = __fmul_rn(g_f0[lo], __fsub_rn(1.0f, frac));
  float b = __fmul_rn(g_f0[hi], frac);
  g_f0up[i] = __fadd_rn(a, b);
}

// pair-sum levels 1..10 (levels 1-2 in registers; identical __fadd_rn tree)
__global__ __launch_bounds__(256) void k_scan_lo() {
  __shared__ float s[256];
  int b = blockIdx.x, t = threadIdx.x;
  float4 x = ((const float4*)g_f0up)[b * 256 + t];
  float a0 = __fadd_rn(x.x, x.y);
  float a1 = __fadd_rn(x.z, x.w);
  float c  = __fadd_rn(a0, a1);
  ((float2*)(g_lv + LVOFF(1)))[b * 256 + t] = make_float2(a0, a1);
  g_lv[LVOFF(2) + b * 256 + t] = c;
  s[t] = c;
  __syncthreads();
  int n = 128;
  #pragma unroll
  for (int l = 3; l <= 10; l++) {
    float v = 0.0f;
    if (t < n) v = __fadd_rn(s[2 * t], s[2 * t + 1]);
    __syncthreads();
    if (t < n) { s[t] = v; g_lv[LVOFF(l) + b * n + t] = v; }
    __syncthreads();
    n >>= 1;
  }
}

// pair-sum levels 11..22, single block (level 10 has 4096 entries)
__global__ __launch_bounds__(1024) void k_scan_hi() {
  __shared__ float s[4096];
  int t = threadIdx.x;
  #pragma unroll
  for (int q = 0; q < 4; q++) s[t + q * 1024] = g_lv[LVOFF(10) + t + q * 1024];
  __syncthreads();
  int n = 2048;
  for (int l = 11; l <= 22; l++) {
    float v0 = 0.0f, v1 = 0.0f;
    if (t < n)        v0 = __fadd_rn(s[2 * t], s[2 * t + 1]);
    if (t + 1024 < n) v1 = __fadd_rn(s[2 * (t + 1024)], s[2 * (t + 1024) + 1]);
    __syncthreads();
    if (t < n)        { s[t] = v0;        g_lv[LVOFF(l) + t] = v0; }
    if (t + 1024 < n) { s[t + 1024] = v1; g_lv[LVOFF(l) + t + 1024] = v1; }
    __syncthreads();
    n >>= 1;
  }
}

// cumsum closed form (jax associative_scan): left-fold of dyadic blocks of [0..n]
__device__ __forceinline__ float saw_at(int n) {
  int m = n + 1;
  float acc = 0.0f;
  bool first = true;
  int start = 0;
  #pragma unroll
  for (int l = 22; l >= 0; --l) {
    if (m & (1 << l)) {
      float v = (l == 0) ? g_f0up[start]
                         : g_lv[LVOFF(l) + (start >> l)];
      acc = first ? v : __fadd_rn(acc, v);
      first = false;
      start += (1 << l);
    }
  }
  float phase = __fdiv_rn(acc, 24000.0f);
  return __fsub_rn(phase, floorf(phase));         // exact frac for phase >= 0
}

// fused saw + impulse (roll(-1) via block-local smem)
__global__ __launch_bounds__(256) void k_sawimp() {
  __shared__ float ssaw[257];
  int base = blockIdx.x * 256;
  int t = threadIdx.x;
  ssaw[t] = saw_at(base + t);
  if (t == 0) ssaw[256] = saw_at((base + 256) & (NSIG - 1));
  __syncthreads();
  float d = __fdiv_rn(g_f0up[base + t], 24000.0f);
  g_pulse[base + t] = __fadd_rn(__fsub_rn(ssaw[t], ssaw[t + 1]), d);
}

// ------------------- envelope transpose [513][16384] -> [16384][513] ------------
__global__ void k_transpose(const float* __restrict__ in, int which) {
  __shared__ float tile[32][33];
  float* out = which ? g_envTp : g_envTn;
  int t0 = blockIdx.x * 32, k0 = blockIdx.y * 32;
  int x = t0 + threadIdx.x, y = k0 + threadIdx.y;
  if (y < NBIN) tile[threadIdx.y][threadIdx.x] = in[(size_t)y * NFR + x];
  __syncthreads();
  int tx = t0 + threadIdx.y, kx = k0 + threadIdx.x;
  if (kx < NBIN) out[(size_t)tx * NBIN + kx] = tile[threadIdx.x][threadIdx.y];
}

// --------------------- shared-memory Stockham radix-4 FFT, N=1024 ---------------
// 256 threads. Input in A (caller synced). Result lands in B.
// One twiddle load per stage (w2=w1^2, w3=w1*w2); stage 0 contiguous STS.128;
// stage 4 (j=0) twiddle-free.
__device__ __forceinline__ float2 cmul_s(float2 b, float2 w, float sgn) {
  float wy = sgn * w.y;
  return make_float2(b.x * w.x - b.y * wy, b.x * wy + b.y * w.x);
}
__device__ __forceinline__ float2 csq(float2 w) {
  return make_float2(w.x * w.x - w.y * w.y, 2.0f * w.x * w.y);
}
__device__ __forceinline__ float2 cmul(float2 a, float2 b) {
  return make_float2(a.x * b.x - a.y * b.y, a.x * b.y + a.y * b.x);
}

__device__ __forceinline__ void fft1024_r4(float2* A, float2* B, int t, bool inv) {
  const float sgn = inv ? -1.0f : 1.0f;
  float2* x = A;
  float2* y = B;
  int m = 1;
  #pragma unroll
  for (int s = 0; s < 4; s++) {
    int j = t >> (2 * s);
    int k = t & (m - 1);
    float2 c0 = x[t];
    float2 c1 = x[t + 256];
    float2 c2 = x[t + 512];
    float2 c3 = x[t + 768];
    float ax = c0.x + c2.x, ay = c0.y + c2.y;
    float bx = c1.x + c3.x, by = c1.y + c3.y;
    float dx = c0.x - c2.x, dy = c0.y - c2.y;
    float ex = c1.x - c3.x, ey = c1.y - c3.y;
    float2 b0 = make_float2(ax + bx, ay + by);
    float2 b2 = make_float2(ax - bx, ay - by);
    float2 b1, b3;
    if (!inv) {
      b1 = make_float2(dx + ey, dy - ex);
      b3 = make_float2(dx - ey, dy + ex);
    } else {
      b1 = make_float2(dx - ey, dy + ex);
      b3 = make_float2(dx + ey, dy - ex);
    }
    int jm = j * m;                 // < 256 always
    float2 w1 = __ldg(&g_tw[jm]);
    float2 w2 = csq(w1);
    float2 w3 = cmul(w1, w2);
    float2 r1 = cmul_s(b1, w1, sgn);
    float2 r2 = cmul_s(b2, w2, sgn);
    float2 r3 = cmul_s(b3, w3, sgn);
    if (s == 0) {                   // o = 4t: contiguous -> 2x STS.128
      float4* y4 = (float4*)y;
      y4[2 * t]     = make_float4(b0.x, b0.y, r1.x, r1.y);
      y4[2 * t + 1] = make_float4(r2.x, r2.y, r3.x, r3.y);
    } else {
      int o = k + 4 * jm;
      y[o]         = b0;
      y[o + m]     = r1;
      y[o + 2 * m] = r2;
      y[o + 3 * m] = r3;
    }
    __syncthreads();
    float2* tp = x; x = y; y = tp;
    m <<= 2;
  }
  // stage 4: m=256, j=0 -> identity twiddles; x==A, write y==B
  {
    float2 c0 = x[t];
    float2 c1 = x[t + 256];
    float2 c2 = x[t + 512];
    float2 c3 = x[t + 768];
    float ax = c0.x + c2.x, ay = c0.y + c2.y;
    float bx = c1.x + c3.x, by = c1.y + c3.y;
    float dx = c0.x - c2.x, dy = c0.y - c2.y;
    float ex = c1.x - c3.x, ey = c1.y - c3.y;
    y[t]       = make_float2(ax + bx, ay + by);
    y[t + 512] = make_float2(ax - bx, ay - by);
    if (!inv) {
      y[t + 256] = make_float2(dx + ey, dy - ex);
      y[t + 768] = make_float2(dx - ey, dy + ex);
    } else {
      y[t + 256] = make_float2(dx - ey, dy + ex);
      y[t + 768] = make_float2(dx + ey, dy - ex);
    }
    __syncthreads();
  }
}

// ------------------------------ per-frame-pair mega-kernel ----------------------
// Block b: frames t0=2b, t1=2b+1. 5 complex FFTs per 2 frames.
// sp*[k] = (N.x, N.y, P.x, P.y) packed float4 per bin.
__global__ __launch_bounds__(256) void k_frames(const float* __restrict__ noise) {
  __shared__ __align__(16) float2 bufA[1024];
  __shared__ __align__(16) float2 bufB[1024];
  __shared__ float4 sp0[NBIN];
  __shared__ float4 sp1[NBIN];

  int b   = blockIdx.x;
  int t0  = 2 * b, t1 = 2 * b + 1;
  int tid = threadIdx.x;

  // ---- analysis FFT, frame t0 (noise + i*pulse) ----
  #pragma unroll
  for (int q = 0; q < 4; q++) {
    int n = tid + q * 256;
    int g = t0 * 256 - 256 + n;                // reflect pad
    if (g < 0) g = -g;
    else if (g >= NSIG) g = 2 * NSIG - 2 - g;
    float w = g_w[n];
    bufA[n] = make_float2(noise[g] * w, g_pulse[g] * w);
  }
  __syncthreads();
  fft1024_r4(bufA, bufB, tid, false);

  // unpack t0 (+ noise envelope); stage frame t1 into bufA
  #pragma unroll
  for (int k = tid; k <= 512; k += 256) {
    float2 z1 = bufB[k];
    float2 z2 = bufB[(1024 - k) & 1023];
    float en = __expf(g_envTn[(size_t)t0 * NBIN + k]);
    sp0[k] = make_float4(0.5f * (z1.x + z2.x) * en, 0.5f * (z1.y - z2.y) * en,
                         0.5f * (z1.y + z2.y),      0.5f * (z2.x - z1.x));
  }
  #pragma unroll
  for (int q = 0; q < 4; q++) {
    int n = tid + q * 256;
    int g = t1 * 256 - 256 + n;
    if (g < 0) g = -g;
    else if (g >= NSIG) g = 2 * NSIG - 2 - g;
    float w = g_w[n];
    bufA[n] = make_float2(noise[g] * w, g_pulse[g] * w);
  }
  __syncthreads();

  fft1024_r4(bufA, bufB, tid, false);

  #pragma unroll
  for (int k = tid; k <= 512; k += 256) {
    float2 z1 = bufB[k];
    float2 z2 = bufB[(1024 - k) & 1023];
    float en = __expf(g_envTn[(size_t)t1 * NBIN + k]);
    sp1[k] = make_float4(0.5f * (z1.x + z2.x) * en, 0.5f * (z1.y - z2.y) * en,
                         0.5f * (z1.y + z2.y),      0.5f * (z2.x - z1.x));
  }
  // packed min-phase input: v_t0 + i*v_t1 (both real even)
  #pragma unroll
  for (int q = 0; q < 4; q++) {
    int n = tid + q * 256;
    int k = (n <= 512) ? n : 1024 - n;
    bufA[n] = make_float2(g_envTp[(size_t)t0 * NBIN + k],
                          g_envTp[(size_t)t1 * NBIN + k]);
  }
  __syncthreads();

  // ---- packed min-phase iDFT: Re=1024*cep_t0, Im=1024*cep_t1 ----
  fft1024_r4(bufA, bufB, tid, true);

  // fold both cepstra
  #pragma unroll
  for (int q = 0; q < 4; q++) {
    int n = tid + q * 256;
    float f = (n == 0 || n == 512) ? 1.0f : (n < 512 ? 2.0f : 0.0f);
    float sc = f * (1.0f / 1024.0f);
    bufA[n] = make_float2(bufB[n].x * sc, bufB[n].y * sc);
  }
  __syncthreads();

  // ---- packed forward FFT of folded cepstra ----
  fft1024_r4(bufA, bufB, tid, false);

  // Hermitian unpack -> C0,C1; exp; combine; build packed synthesis spectrum
  #pragma unroll
  for (int k = tid; k <= 512; k += 256) {
    float2 z  = bufB[k];
    float2 zm = bufB[(1024 - k) & 1023];
    float2 C0 = make_float2(0.5f * (z.x + zm.x),  0.5f * (z.y - zm.y));
    float2 C1 = make_float2(0.5f * (z.y + zm.y), -0.5f * (z.x - zm.x));
    float sn, cs;
    float m0 = __expf(C0.x);
    __sincosf(C0.y, &sn, &cs);
    float2 MP0 = make_float2(m0 * cs, m0 * sn);
    float m1 = __expf(C1.x);
    __sincosf(C1.y, &sn, &cs);
    float2 MP1 = make_float2(m1 * cs, m1 * sn);

    float4 v0 = sp0[k], v1 = sp1[k];
    float2 S0 = make_float2(v0.x + v0.z * MP0.x - v0.w * MP0.y,
                            v0.y + v0.z * MP0.y + v0.w * MP0.x);
    float2 S1 = make_float2(v1.x + v1.z * MP1.x - v1.w * MP1.y,
                            v1.y + v1.z * MP1.y + v1.w * MP1.x);
    if (k == 0 || k == 512) { S0.y = 0.0f; S1.y = 0.0f; }  // irfft drops these

    bufA[k] = make_float2(S0.x - S1.y, S0.y + S1.x);
    if (k > 0 && k < 512)
      bufA[1024 - k] = make_float2(S0.x + S1.y, S1.x - S0.y);
  }
  __syncthreads();

  // ---- packed synthesis iFFT: Re=1024*frame_t0, Im=1024*frame_t1 ----
  fft1024_r4(bufA, bufB, tid, true);

  #pragma unroll
  for (int q = 0; q < 4; q++) {
    int n = tid + q * 256;
    float ws = (1.0f / 1024.0f) * g_w[n];
    float2 v = bufB[n];
    g_frames[(size_t)t0 * 1024 + n] = v.x * ws;
    g_frames[(size_t)t1 * 1024 + n] = v.y * ws;
  }
}

// ----------------------------- overlap-add + wsq -------------------------------
__global__ void k_ola(float* __restrict__ out) {
  int i = blockIdx.x * blockDim.x + threadIdx.x;
  if (i >= OUTLEN) return;
  int p = i + 512;                 // position in padded iSTFT output
  int jhi = p >> 8;
  int jlo = jhi - 3;
  if (jlo < 0) jlo = 0;
  if (jhi > NFR - 1) jhi = NFR - 1;
  float acc = 0.0f, ws = 0.0f;
  #pragma unroll 4
  for (int j = jlo; j <= jhi; j++) {
    int n = p - (j << 8);
    acc += g_frames[(size_t)j * 1024 + n];
    float w = g_w[n];
    ws += w * w;
  }
  out[i] = acc / fmaxf(ws, 1e-11f);
}

// --------------------------------- launcher ------------------------------------
extern "C" void kernel_launch(void* const* d_in, const int* in_sizes, int n_in,
                              void* d_out, int out_size) {
  const float* log_f0  = (const float*)d_in[0];
  const float* env_noi = (const float*)d_in[1];
  const float* env_per = (const float*)d_in[2];
  const float* noise   = (const float*)d_in[3];
  float* out = (float*)d_out;

  k_init<<<1, 1024>>>();
  k_exp<<<NFR / 256, 256>>>(log_f0);
  k_interp<<<NSIG / 256, 256>>>();
  k_scan_lo<<<NSIG / 1024, 256>>>();
  k_scan_hi<<<1, 1024>>>();
  k_sawimp<<<NSIG / 256, 256>>>();
  dim3 tb(32, 32);
  dim3 tg(NFR / 32, (NBIN + 31) / 32);
  k_transpose<<<tg, tb>>>(env_noi, 0);
  k_transpose<<<tg, tb>>>(env_per, 1);
  k_frames<<<NFR / 2, 256>>>(noise);
  k_ola<<<(OUTLEN + 255) / 256, 256>>>(out);
}

// round 7
// speedup vs baseline: 2.0388x; 1.0903x over previous
#include <cuda_runtime.h>
#include <math.h>

#define NSIG   (1 << 22)              // 4194304 = HOP * N_FRAMES
#define NFR    16384
#define NBIN   513
#define HOPSZ  256
#define OUTLEN ((NFR - 1) * HOPSZ)    // 4194048
#define LVOFF(l) ((1 << 22) - (1 << (23 - (l))))

// ------------------------- device scratch (static per rules) -------------------
__device__ float  g_f0[NFR];
__device__ float  g_f0up[NSIG];
__device__ float  g_lv[NSIG];                    // pair-sum levels 1..22 packed
__device__ float  g_pulse[NSIG];
__device__ float  g_envTn[(size_t)NFR * NBIN];   // transposed log-envelopes [t][k]
__device__ float  g_envTp[(size_t)NFR * NBIN];
__device__ float  g_frames[(size_t)NFR * 1024];  // windowed synthesis frames
__device__ float2 g_tw[256];                     // exp(-2*pi*i*t/1024), t<256
__device__ float  g_w[1024];                     // hann window

// ------------------------------- init tables -----------------------------------
__global__ void k_init() {
  int tid = threadIdx.x;                          // <<<1,1024>>>
  if (tid < 256) {
    double ang = -2.0 * 3.14159265358979323846 * (double)tid / 1024.0;
    g_tw[tid] = make_float2((float)cos(ang), (float)sin(ang));
  }
  g_w[tid] = 0.5f * (1.0f - cosf((float)tid * (6.28318530717958647692f / 1024.0f)));
}

// --------------------- impulse train (bit-replicates JAX) ----------------------
__global__ void k_exp(const float* __restrict__ log_f0) {
  int i = blockIdx.x * blockDim.x + threadIdx.x;
  if (i < NFR) g_f0[i] = expf(log_f0[i]);
}

__global__ void k_interp() {
  int i = blockIdx.x * blockDim.x + threadIdx.x;
  float fi  = (float)i;
  float pos = __fsub_rn(__fdiv_rn(__fadd_rn(fi, 0.5f), 256.0f), 0.5f);
  pos = fminf(fmaxf(pos, 0.0f), 16383.0f);
  float flo = floorf(pos);
  int lo = (int)flo;
  int hi = lo + 1; if (hi > 16383) hi = 16383;
  float frac = __fsub_rn(pos, flo);
  float a = __fmul_rn(g_f0[lo], __fsub_rn(1.0f, frac));
  float b = __fmul_rn(g_f0[hi], frac);
  g_f0up[i] = __fadd_rn(a, b);
}

// pair-sum levels 1..10 (levels 1-2 in registers; identical __fadd_rn tree)
__global__ __launch_bounds__(256) void k_scan_lo() {
  __shared__ float s[256];
  int b = blockIdx.x, t = threadIdx.x;
  float4 x = ((const float4*)g_f0up)[b * 256 + t];
  float a0 = __fadd_rn(x.x, x.y);
  float a1 = __fadd_rn(x.z, x.w);
  float c  = __fadd_rn(a0, a1);
  ((float2*)(g_lv + LVOFF(1)))[b * 256 + t] = make_float2(a0, a1);
  g_lv[LVOFF(2) + b * 256 + t] = c;
  s[t] = c;
  __syncthreads();
  int n = 128;
  #pragma unroll
  for (int l = 3; l <= 10; l++) {
    float v = 0.0f;
    if (t < n) v = __fadd_rn(s[2 * t], s[2 * t + 1]);
    __syncthreads();
    if (t < n) { s[t] = v; g_lv[LVOFF(l) + b * n + t] = v; }
    __syncthreads();
    n >>= 1;
  }
}

// pair-sum levels 11..22, single block
__global__ __launch_bounds__(1024) void k_scan_hi() {
  __shared__ float s[4096];
  int t = threadIdx.x;
  #pragma unroll
  for (int q = 0; q < 4; q++) s[t + q * 1024] = g_lv[LVOFF(10) + t + q * 1024];
  __syncthreads();
  int n = 2048;
  for (int l = 11; l <= 22; l++) {
    float v0 = 0.0f, v1 = 0.0f;
    if (t < n)        v0 = __fadd_rn(s[2 * t], s[2 * t + 1]);
    if (t + 1024 < n) v1 = __fadd_rn(s[2 * (t + 1024)], s[2 * (t + 1024) + 1]);
    __syncthreads();
    if (t < n)        { s[t] = v0;        g_lv[LVOFF(l) + t] = v0; }
    if (t + 1024 < n) { s[t + 1024] = v1; g_lv[LVOFF(l) + t + 1024] = v1; }
    __syncthreads();
    n >>= 1;
  }
}

// cumsum closed form (jax associative_scan): left-fold of dyadic blocks of [0..n]
__device__ __forceinline__ float saw_at(int n) {
  int m = n + 1;
  float acc = 0.0f;
  bool first = true;
  int start = 0;
  #pragma unroll
  for (int l = 22; l >= 0; --l) {
    if (m & (1 << l)) {
      float v = (l == 0) ? g_f0up[start]
                         : g_lv[LVOFF(l) + (start >> l)];
      acc = first ? v : __fadd_rn(acc, v);
      first = false;
      start += (1 << l);
    }
  }
  float phase = __fdiv_rn(acc, 24000.0f);
  return __fsub_rn(phase, floorf(phase));
}

__global__ __launch_bounds__(256) void k_sawimp() {
  __shared__ float ssaw[257];
  int base = blockIdx.x * 256;
  int t = threadIdx.x;
  ssaw[t] = saw_at(base + t);
  if (t == 0) ssaw[256] = saw_at((base + 256) & (NSIG - 1));
  __syncthreads();
  float d = __fdiv_rn(g_f0up[base + t], 24000.0f);
  g_pulse[base + t] = __fadd_rn(__fsub_rn(ssaw[t], ssaw[t + 1]), d);
}

// ------------------- envelope transpose [513][16384] -> [16384][513] ------------
__global__ void k_transpose(const float* __restrict__ in, int which) {
  __shared__ float tile[32][33];
  float* out = which ? g_envTp : g_envTn;
  int t0 = blockIdx.x * 32, k0 = blockIdx.y * 32;
  int x = t0 + threadIdx.x, y = k0 + threadIdx.y;
  if (y < NBIN) tile[threadIdx.y][threadIdx.x] = in[(size_t)y * NFR + x];
  __syncthreads();
  int tx = t0 + threadIdx.y, kx = k0 + threadIdx.x;
  if (kx < NBIN) out[(size_t)tx * NBIN + kx] = tile[threadIdx.x][threadIdx.y];
}

// ------------------------ register FFT building blocks -------------------------
__device__ __forceinline__ float2 cmul(float2 a, float2 b) {
  return make_float2(a.x * b.x - a.y * b.y, a.x * b.y + a.y * b.x);
}

// sgn=+1 forward (W4 = -i), sgn=-1 inverse
__device__ __forceinline__ void dft4(float2& x0, float2& x1, float2& x2, float2& x3,
                                     float sgn) {
  float t0x = x0.x + x2.x, t0y = x0.y + x2.y;
  float t1x = x0.x - x2.x, t1y = x0.y - x2.y;
  float t2x = x1.x + x3.x, t2y = x1.y + x3.y;
  float t3x = x1.x - x3.x, t3y = x1.y - x3.y;
  x0 = make_float2(t0x + t2x, t0y + t2y);
  x2 = make_float2(t0x - t2x, t0y - t2y);
  x1 = make_float2(t1x + sgn * t3y, t1y - sgn * t3x);
  x3 = make_float2(t1x - sgn * t3y, t1y + sgn * t3x);
}

__device__ __forceinline__ void dft8(float2 c[8], float sgn) {
  const float R2 = 0.70710678118654752f;
  float2 e0 = c[0], e1 = c[2], e2 = c[4], e3 = c[6];
  float2 o0 = c[1], o1 = c[3], o2 = c[5], o3 = c[7];
  dft4(e0, e1, e2, e3, sgn);
  dft4(o0, o1, o2, o3, sgn);
  float2 T1 = make_float2(R2 * (o1.x + sgn * o1.y), R2 * (o1.y - sgn * o1.x));
  float2 T2 = make_float2(sgn * o2.y, -sgn * o2.x);
  float2 T3 = make_float2(R2 * (sgn * o3.y - o3.x), R2 * (-sgn * o3.x - o3.y));
  c[0] = make_float2(e0.x + o0.x, e0.y + o0.y);
  c[4] = make_float2(e0.x - o0.x, e0.y - o0.y);
  c[1] = make_float2(e1.x + T1.x, e1.y + T1.y);
  c[5] = make_float2(e1.x - T1.x, e1.y - T1.y);
  c[2] = make_float2(e2.x + T2.x, e2.y + T2.y);
  c[6] = make_float2(e2.x - T2.x, e2.y - T2.y);
  c[3] = make_float2(e3.x + T3.x, e3.y + T3.y);
  c[7] = make_float2(e3.x - T3.x, e3.y - T3.y);
}

__device__ __forceinline__ void dft16(float2 c[16], float sgn) {
  const float C1 = 0.92387953251128676f;   // cos(pi/8)
  const float S1 = 0.38268343236508977f;   // sin(pi/8)
  const float R2 = 0.70710678118654752f;
  float2 e[8], o[8];
  #pragma unroll
  for (int q = 0; q < 8; q++) { e[q] = c[2 * q]; o[q] = c[2 * q + 1]; }
  dft8(e, sgn);
  dft8(o, sgn);
  float2 w[8];
  w[0] = make_float2(1.0f, 0.0f);
  w[1] = make_float2(C1, -sgn * S1);
  w[2] = make_float2(R2, -sgn * R2);
  w[3] = make_float2(S1, -sgn * C1);
  w[4] = make_float2(0.0f, -sgn);
  w[5] = make_float2(-S1, -sgn * C1);
  w[6] = make_float2(-R2, -sgn * R2);
  w[7] = make_float2(-C1, -sgn * S1);
  #pragma unroll
  for (int r = 0; r < 8; r++) {
    float2 T = cmul(o[r], w[r]);
    c[r]     = make_float2(e[r].x + T.x, e[r].y + T.y);
    c[r + 8] = make_float2(e[r].x - T.x, e[r].y - T.y);
  }
}

// padded smem index: kills bank conflicts for all stage patterns
__device__ __forceinline__ int SW(int i) { return i + (i >> 4); }
#define WSN 1088

// 1024-pt FFT, 128 threads per group (t in [0,128)). Input in A (caller synced),
// output in B. Stages: radix-8 (m=1), radix-8 (m=8), radix-16 (m=64, twiddle-free).
__device__ void fftg(float2* A, float2* B, int t, bool inv) {
  const float sgn = inv ? -1.0f : 1.0f;
  { // stage 1: radix-8, m=1, j=t
    float2 c[8];
    #pragma unroll
    for (int q = 0; q < 8; q++) c[q] = A[SW(t + 128 * q)];
    dft8(c, sgn);
    float2 w0 = __ldg(&g_tw[t]);
    float2 wc = make_float2(w0.x, sgn * w0.y);
    float2 u = wc;
    c[1] = cmul(c[1], u);
    #pragma unroll
    for (int r = 2; r < 8; r++) { u = cmul(u, wc); c[r] = cmul(c[r], u); }
    #pragma unroll
    for (int r = 0; r < 8; r++) B[SW(8 * t + r)] = c[r];
  }
  __syncthreads();
  { // stage 2: radix-8, m=8
    float2 c[8];
    #pragma unroll
    for (int q = 0; q < 8; q++) c[q] = B[SW(t + 128 * q)];
    dft8(c, sgn);
    int j = t >> 3, k = t & 7;
    float2 w0 = __ldg(&g_tw[8 * j]);
    float2 wc = make_float2(w0.x, sgn * w0.y);
    float2 u = wc;
    c[1] = cmul(c[1], u);
    #pragma unroll
    for (int r = 2; r < 8; r++) { u = cmul(u, wc); c[r] = cmul(c[r], u); }
    int o = k + 64 * j;
    #pragma unroll
    for (int r = 0; r < 8; r++) A[SW(o + 8 * r)] = c[r];
  }
  __syncthreads();
  if (t < 64) { // stage 3: radix-16, m=64, j=0 -> no twiddles
    float2 c[16];
    #pragma unroll
    for (int q = 0; q < 16; q++) c[q] = A[SW(t + 64 * q)];
    dft16(c, sgn);
    #pragma unroll
    for (int r = 0; r < 16; r++) B[SW(t + 64 * r)] = c[r];
  }
  __syncthreads();
}

// ------------------------------ per-4-frame mega-kernel -------------------------
// Block handles frames 4b..4b+3. Group g (threads 128g..128g+127) owns the pair
// (4b+2g, 4b+2g+1). 5 FFT rounds, both groups busy every round.
// All per-bin spectra (MP, S) stay in registers (bin k = tt+128q is same-thread).
__global__ __launch_bounds__(256) void k_frames(const float* __restrict__ noise) {
  __shared__ __align__(16) float2 ws[2][2][WSN];

  int tid = threadIdx.x;
  int g  = tid >> 7;
  int tt = tid & 127;
  int f0 = 4 * blockIdx.x + 2 * g;
  int f1 = f0 + 1;
  float2* WA = ws[g][0];
  float2* WB = ws[g][1];

  // ---- phase 1: packed min-phase input (log-env of f0 + i*f1, symmetric) ----
  #pragma unroll
  for (int q = 0; q < 8; q++) {
    int n = tt + 128 * q;
    int k = (n <= 512) ? n : 1024 - n;
    WA[SW(n)] = make_float2(g_envTp[(size_t)f0 * NBIN + k],
                            g_envTp[(size_t)f1 * NBIN + k]);
  }
  __syncthreads();
  fftg(WA, WB, tt, true);          // cep0*1024 in Re, cep1*1024 in Im

  // ---- phase 2: fold ----
  #pragma unroll
  for (int q = 0; q < 8; q++) {
    int n = tt + 128 * q;
    float f = (n == 0 || n == 512) ? 1.0f : (n < 512 ? 2.0f : 0.0f);
    float sc = f * (1.0f / 1024.0f);
    float2 v = WB[SW(n)];
    WA[SW(n)] = make_float2(v.x * sc, v.y * sc);
  }
  __syncthreads();
  fftg(WA, WB, tt, false);         // packed C spectra

  // ---- phase 3: min-phase exp -> registers ----
  float2 MP0[5], MP1[5];
  #pragma unroll
  for (int q = 0; q < 5; q++) {
    int k = tt + 128 * q;
    if (k <= 512) {
      float2 z  = WB[SW(k)];
      float2 zm = WB[SW((1024 - k) & 1023)];
      float2 C0 = make_float2(0.5f * (z.x + zm.x),  0.5f * (z.y - zm.y));
      float2 C1 = make_float2(0.5f * (z.y + zm.y), -0.5f * (z.x - zm.x));
      float sn, cs;
      float m0 = __expf(C0.x);
      __sincosf(C0.y, &sn, &cs);
      MP0[q] = make_float2(m0 * cs, m0 * sn);
      float m1 = __expf(C1.x);
      __sincosf(C1.y, &sn, &cs);
      MP1[q] = make_float2(m1 * cs, m1 * sn);
    }
  }

  // ---- phase 4: analysis FFT frame f0 (noise + i*pulse) ----
  #pragma unroll
  for (int q = 0; q < 8; q++) {
    int n = tt + 128 * q;
    int gi = f0 * 256 - 256 + n;
    if (gi < 0) gi = -gi;
    else if (gi >= NSIG) gi = 2 * NSIG - 2 - gi;
    float w = g_w[n];
    WA[SW(n)] = make_float2(noise[gi] * w, g_pulse[gi] * w);
  }
  __syncthreads();
  fftg(WA, WB, tt, false);

  float2 S0[5];
  #pragma unroll
  for (int q = 0; q < 5; q++) {
    int k = tt + 128 * q;
    if (k <= 512) {
      float2 z1 = WB[SW(k)];
      float2 z2 = WB[SW((1024 - k) & 1023)];
      float en = __expf(g_envTn[(size_t)f0 * NBIN + k]);
      float2 N = make_float2(0.5f * (z1.x + z2.x) * en, 0.5f * (z1.y - z2.y) * en);
      float2 P = make_float2(0.5f * (z1.y + z2.y),      0.5f * (z2.x - z1.x));
      float2 PM = cmul(P, MP0[q]);
      S0[q] = make_float2(N.x + PM.x, N.y + PM.y);
    }
  }

  // ---- phase 5: analysis FFT frame f1, combine, build packed synth spectrum ----
  #pragma unroll
  for (int q = 0; q < 8; q++) {
    int n = tt + 128 * q;
    int gi = f1 * 256 - 256 + n;
    if (gi < 0) gi = -gi;
    else if (gi >= NSIG) gi = 2 * NSIG - 2 - gi;
    float w = g_w[n];
    WA[SW(n)] = make_float2(noise[gi] * w, g_pulse[gi] * w);
  }
  __syncthreads();
  fftg(WA, WB, tt, false);

  #pragma unroll
  for (int q = 0; q < 5; q++) {
    int k = tt + 128 * q;
    if (k <= 512) {
      float2 z1 = WB[SW(k)];
      float2 z2 = WB[SW((1024 - k) & 1023)];
      float en = __expf(g_envTn[(size_t)f1 * NBIN + k]);
      float2 N = make_float2(0.5f * (z1.x + z2.x) * en, 0.5f * (z1.y - z2.y) * en);
      float2 P = make_float2(0.5f * (z1.y + z2.y),      0.5f * (z2.x - z1.x));
      float2 PM = cmul(P, MP1[q]);
      float2 s1 = make_float2(N.x + PM.x, N.y + PM.y);
      float2 s0 = S0[q];
      if (k == 0 || k == 512) { s0.y = 0.0f; s1.y = 0.0f; }   // irfft drops these
      WA[SW(k)] = make_float2(s0.x - s1.y, s0.y + s1.x);
      if (k > 0 && k < 512)
        WA[SW(1024 - k)] = make_float2(s0.x + s1.y, s1.x - s0.y);
    }
  }
  __syncthreads();

  // ---- phase 6: packed synthesis iFFT, window, store both frames ----
  fftg(WA, WB, tt, true);

  #pragma unroll
  for (int q = 0; q < 8; q++) {
    int n = tt + 128 * q;
    float wsc = (1.0f / 1024.0f) * g_w[n];
    float2 v = WB[SW(n)];
    g_frames[(size_t)f0 * 1024 + n] = v.x * wsc;
    g_frames[(size_t)f1 * 1024 + n] = v.y * wsc;
  }
}

// ----------------------------- overlap-add + wsq -------------------------------
__global__ void k_ola(float* __restrict__ out) {
  int i = blockIdx.x * blockDim.x + threadIdx.x;
  if (i >= OUTLEN) return;
  int p = i + 512;
  int jhi = p >> 8;
  int jlo = jhi - 3;
  if (jlo < 0) jlo = 0;
  if (jhi > NFR - 1) jhi = NFR - 1;
  float acc = 0.0f, wsq = 0.0f;
  #pragma unroll 4
  for (int j = jlo; j <= jhi; j++) {
    int n = p - (j << 8);
    acc += g_frames[(size_t)j * 1024 + n];
    float w = g_w[n];
    wsq += w * w;
  }
  out[i] = acc / fmaxf(wsq, 1e-11f);
}

// --------------------------------- launcher ------------------------------------
extern "C" void kernel_launch(void* const* d_in, const int* in_sizes, int n_in,
                              void* d_out, int out_size) {
  const float* log_f0  = (const float*)d_in[0];
  const float* env_noi = (const float*)d_in[1];
  const float* env_per = (const float*)d_in[2];
  const float* noise   = (const float*)d_in[3];
  float* out = (float*)d_out;

  k_init<<<1, 1024>>>();
  k_exp<<<NFR / 256, 256>>>(log_f0);
  k_interp<<<NSIG / 256, 256>>>();
  k_scan_lo<<<NSIG / 1024, 256>>>();
  k_scan_hi<<<1, 1024>>>();
  k_sawimp<<<NSIG / 256, 256>>>();
  dim3 tb(32, 32);
  dim3 tg(NFR / 32, (NBIN + 31) / 32);
  k_transpose<<<tg, tb>>>(env_noi, 0);
  k_transpose<<<tg, tb>>>(env_per, 1);
  k_frames<<<NFR / 4, 256>>>(noise);
  k_ola<<<(OUTLEN + 255) / 256, 256>>>(out);
}